// round 12
// baseline (speedup 1.0000x reference)
#include <cuda_runtime.h>
#include <cuda_fp16.h>
#include <math.h>
#include <stdint.h>

#define NN 50000
#define HH 4
#define CC 32
#define F1 128
#define F2 64
#define NEG 0.2f
#define EPSV 1e-16f
#define EMAX 1600000   // real edges only (self loops handled analytically)
#define NBLK ((NN + 255) / 256)

// ---------------- scratch (device globals; no allocations allowed) ----------
__device__ __align__(16) __half g_xw1h[NN * F1];  // x@W1 half (agg1 gather)
__device__ float  g_h1 [NN * F1];                 // layer1 output (gemm2 input)
__device__ float  g_asrc1[NN * HH];
__device__ float  g_adst1[NN * HH];
__device__ __align__(16) __half g_xw2h[NN * F2];  // h@W2 half (agg2 gather)
__device__ float  g_asrc2[NN];
__device__ float  g_adst2[NN];
__device__ int    g_deg[NN];          // ZERO before each use; scanA re-zeroes
__device__ int    g_off[NN];          // CSR segment start
__device__ int    g_cur[NN];          // scatter cursor
__device__ int    g_bsum[256];        // block sums for scan
__device__ int    g_csr[EMAX];        // src node per edge, grouped by dst

// ---------------- GEMM1: xw1h = half(x @ W1), fused attn1 -------------------
__global__ __launch_bounds__(256) void gemm1_kernel(
    const float* __restrict__ A, const float* __restrict__ B,
    __half* __restrict__ Ch,
    const float* __restrict__ att_src, const float* __restrict__ att_dst, int M)
{
    const int BM = 128, BN = 128, BK = 8, KTOT = 128, NT = 256, TX = 16;
    __shared__ float As[2][BK * BM];
    __shared__ float Bs[2][BK * BN];

    int tid = threadIdx.x;
    int tx = tid % TX;
    int ty = tid / TX;
    int row0 = blockIdx.y * BM;

    float acc[8][8] = {};

    auto load_tile = [&](int buf, int kt) {
        int k0 = kt * BK;
        #pragma unroll
        for (int idx = tid; idx < BM * BK / 4; idx += NT) {
            int row = idx >> 1;
            int kc  = (idx & 1) * 4;
            int gr = row0 + row;
            float4 v = make_float4(0.f, 0.f, 0.f, 0.f);
            if (gr < M) v = *(const float4*)(A + (size_t)gr * KTOT + k0 + kc);
            As[buf][(kc + 0) * BM + row] = v.x;
            As[buf][(kc + 1) * BM + row] = v.y;
            As[buf][(kc + 2) * BM + row] = v.z;
            As[buf][(kc + 3) * BM + row] = v.w;
        }
        #pragma unroll
        for (int idx = tid; idx < BK * BN / 4; idx += NT) {
            int r  = idx / (BN / 4);
            int c4 = (idx % (BN / 4)) * 4;
            *(float4*)&Bs[buf][r * BN + c4] =
                *(const float4*)(B + (size_t)(k0 + r) * BN + c4);
        }
    };

    load_tile(0, 0);
    __syncthreads();

    int buf = 0;
    for (int kt = 0; kt < KTOT / BK; kt++) {
        if (kt + 1 < KTOT / BK) load_tile(buf ^ 1, kt + 1);
        #pragma unroll
        for (int kk = 0; kk < BK; kk++) {
            float4 a0 = *(const float4*)&As[buf][kk * BM + ty * 8];
            float4 a1 = *(const float4*)&As[buf][kk * BM + ty * 8 + 4];
            float4 b0 = *(const float4*)&Bs[buf][kk * BN + tx * 8];
            float4 b1 = *(const float4*)&Bs[buf][kk * BN + tx * 8 + 4];
            float av[8] = {a0.x,a0.y,a0.z,a0.w,a1.x,a1.y,a1.z,a1.w};
            float bv[8] = {b0.x,b0.y,b0.z,b0.w,b1.x,b1.y,b1.z,b1.w};
            #pragma unroll
            for (int i = 0; i < 8; i++)
                #pragma unroll
                for (int j = 0; j < 8; j++)
                    acc[i][j] = fmaf(av[i], bv[j], acc[i][j]);
        }
        __syncthreads();
        buf ^= 1;
    }

    float as1[8], ad1[8];
    #pragma unroll
    for (int j = 0; j < 8; j++) {
        as1[j] = att_src[tx * 8 + j];
        ad1[j] = att_dst[tx * 8 + j];
    }
    int h = tx >> 2;

    #pragma unroll
    for (int i = 0; i < 8; i++) {
        int gr = row0 + ty * 8 + i;
        float ps = 0.f, pd = 0.f;
        #pragma unroll
        for (int j = 0; j < 8; j++) {
            ps = fmaf(acc[i][j], as1[j], ps);
            pd = fmaf(acc[i][j], ad1[j], pd);
        }
        ps += __shfl_xor_sync(0xffffffffu, ps, 1);
        pd += __shfl_xor_sync(0xffffffffu, pd, 1);
        ps += __shfl_xor_sync(0xffffffffu, ps, 2);
        pd += __shfl_xor_sync(0xffffffffu, pd, 2);
        if (gr < M) {
            __half2 p0 = __floats2half2_rn(acc[i][0], acc[i][1]);
            __half2 p1 = __floats2half2_rn(acc[i][2], acc[i][3]);
            __half2 p2 = __floats2half2_rn(acc[i][4], acc[i][5]);
            __half2 p3 = __floats2half2_rn(acc[i][6], acc[i][7]);
            uint4 u = make_uint4(*(unsigned*)&p0, *(unsigned*)&p1,
                                 *(unsigned*)&p2, *(unsigned*)&p3);
            *(uint4*)(Ch + (size_t)gr * BN + tx * 8) = u;
            if ((tx & 3) == 0) {
                g_asrc1[gr * 4 + h] = ps;
                g_adst1[gr * 4 + h] = pd;
            }
        }
    }
}

// ---------------- GEMM2: xw2h = half(h1 @ W2), fused attn2 ------------------
__global__ __launch_bounds__(128) void gemm2_kernel(
    const float* __restrict__ A, const float* __restrict__ B,
    __half* __restrict__ Ch,
    const float* __restrict__ att_src, const float* __restrict__ att_dst, int M)
{
    const int BM = 128, BN = 64, BK = 8, KTOT = 128, NT = 128, TX = 8;
    __shared__ float As[2][BK * BM];
    __shared__ float Bs[2][BK * BN];

    int tid = threadIdx.x;
    int tx = tid % TX;
    int ty = tid / TX;
    int row0 = blockIdx.y * BM;

    float acc[8][8] = {};

    auto load_tile = [&](int buf, int kt) {
        int k0 = kt * BK;
        #pragma unroll
        for (int idx = tid; idx < BM * BK / 4; idx += NT) {
            int row = idx >> 1;
            int kc  = (idx & 1) * 4;
            int gr = row0 + row;
            float4 v = make_float4(0.f, 0.f, 0.f, 0.f);
            if (gr < M) v = *(const float4*)(A + (size_t)gr * KTOT + k0 + kc);
            As[buf][(kc + 0) * BM + row] = v.x;
            As[buf][(kc + 1) * BM + row] = v.y;
            As[buf][(kc + 2) * BM + row] = v.z;
            As[buf][(kc + 3) * BM + row] = v.w;
        }
        #pragma unroll
        for (int idx = tid; idx < BK * BN / 4; idx += NT) {
            int r  = idx / (BN / 4);
            int c4 = (idx % (BN / 4)) * 4;
            *(float4*)&Bs[buf][r * BN + c4] =
                *(const float4*)(B + (size_t)(k0 + r) * BN + c4);
        }
    };

    load_tile(0, 0);
    __syncthreads();

    int buf = 0;
    for (int kt = 0; kt < KTOT / BK; kt++) {
        if (kt + 1 < KTOT / BK) load_tile(buf ^ 1, kt + 1);
        #pragma unroll
        for (int kk = 0; kk < BK; kk++) {
            float4 a0 = *(const float4*)&As[buf][kk * BM + ty * 8];
            float4 a1 = *(const float4*)&As[buf][kk * BM + ty * 8 + 4];
            float4 b0 = *(const float4*)&Bs[buf][kk * BN + tx * 8];
            float4 b1 = *(const float4*)&Bs[buf][kk * BN + tx * 8 + 4];
            float av[8] = {a0.x,a0.y,a0.z,a0.w,a1.x,a1.y,a1.z,a1.w};
            float bv[8] = {b0.x,b0.y,b0.z,b0.w,b1.x,b1.y,b1.z,b1.w};
            #pragma unroll
            for (int i = 0; i < 8; i++)
                #pragma unroll
                for (int j = 0; j < 8; j++)
                    acc[i][j] = fmaf(av[i], bv[j], acc[i][j]);
        }
        __syncthreads();
        buf ^= 1;
    }

    float as2[8], ad2[8];
    #pragma unroll
    for (int j = 0; j < 8; j++) {
        as2[j] = att_src[tx * 8 + j];
        ad2[j] = att_dst[tx * 8 + j];
    }

    #pragma unroll
    for (int i = 0; i < 8; i++) {
        int gr = row0 + ty * 8 + i;
        float ps = 0.f, pd = 0.f;
        #pragma unroll
        for (int j = 0; j < 8; j++) {
            ps = fmaf(acc[i][j], as2[j], ps);
            pd = fmaf(acc[i][j], ad2[j], pd);
        }
        ps += __shfl_xor_sync(0xffffffffu, ps, 1);
        pd += __shfl_xor_sync(0xffffffffu, pd, 1);
        ps += __shfl_xor_sync(0xffffffffu, ps, 2);
        pd += __shfl_xor_sync(0xffffffffu, pd, 2);
        ps += __shfl_xor_sync(0xffffffffu, ps, 4);
        pd += __shfl_xor_sync(0xffffffffu, pd, 4);
        if (gr < M) {
            __half2 p0 = __floats2half2_rn(acc[i][0], acc[i][1]);
            __half2 p1 = __floats2half2_rn(acc[i][2], acc[i][3]);
            __half2 p2 = __floats2half2_rn(acc[i][4], acc[i][5]);
            __half2 p3 = __floats2half2_rn(acc[i][6], acc[i][7]);
            uint4 u = make_uint4(*(unsigned*)&p0, *(unsigned*)&p1,
                                 *(unsigned*)&p2, *(unsigned*)&p3);
            *(uint4*)(Ch + (size_t)gr * BN + tx * 8) = u;
            if (tx == 0) {
                g_asrc2[gr] = ps;
                g_adst2[gr] = pd;
            }
        }
    }
}

// ---------------- CSR build (real edges only) -------------------------------
__global__ __launch_bounds__(256) void hist8_kernel(const int* __restrict__ dstp, int E) {
    int i = blockIdx.x * blockDim.x + threadIdx.x;
    int e8 = i * 8;
    if (e8 + 7 < E) {
        int4 a = *(const int4*)(dstp + e8);
        int4 b = *(const int4*)(dstp + e8 + 4);
        atomicAdd(&g_deg[a.x], 1); atomicAdd(&g_deg[a.y], 1);
        atomicAdd(&g_deg[a.z], 1); atomicAdd(&g_deg[a.w], 1);
        atomicAdd(&g_deg[b.x], 1); atomicAdd(&g_deg[b.y], 1);
        atomicAdd(&g_deg[b.z], 1); atomicAdd(&g_deg[b.w], 1);
    } else {
        for (int e = e8; e < E; e++) atomicAdd(&g_deg[dstp[e]], 1);
    }
}

__global__ __launch_bounds__(256) void hist1_kernel(const int* __restrict__ dstp, int E) {
    int e = blockIdx.x * blockDim.x + threadIdx.x;
    if (e < E) atomicAdd(&g_deg[dstp[e]], 1);
}

// per-block exclusive scan of g_deg -> g_off(local), g_bsum; zeroes g_deg
__global__ __launch_bounds__(256) void scanA_kernel() {
    __shared__ int wsum[8];
    int t = threadIdx.x, lane = t & 31, w = t >> 5;
    int idx = blockIdx.x * 256 + t;
    int v = (idx < NN) ? g_deg[idx] : 0;
    int x = v;
    #pragma unroll
    for (int o = 1; o < 32; o <<= 1) {
        int tt = __shfl_up_sync(0xffffffffu, x, o);
        if (lane >= o) x += tt;
    }
    if (lane == 31) wsum[w] = x;
    __syncthreads();
    if (w == 0) {
        int s = (lane < 8) ? wsum[lane] : 0;
        #pragma unroll
        for (int o = 1; o < 8; o <<= 1) {
            int tt = __shfl_up_sync(0xffffffffu, s, o);
            if (lane >= o) s += tt;
        }
        if (lane < 8) wsum[lane] = s;
    }
    __syncthreads();
    int pre = (w > 0 ? wsum[w - 1] : 0) + (x - v);
    if (idx < NN) {
        g_off[idx] = pre;
        g_deg[idx] = 0;               // self-clean for next invocation
    }
    if (t == 255) g_bsum[blockIdx.x] = pre + v;
}

// add block offset (reduce prefix of g_bsum inline), init cursors
__global__ __launch_bounds__(256) void scanC_kernel() {
    __shared__ int wsum[8];
    __shared__ int s_total;
    int t = threadIdx.x, lane = t & 31, w = t >> 5;
    int v = (t < (int)blockIdx.x && t < NBLK) ? g_bsum[t] : 0;
    #pragma unroll
    for (int o = 16; o > 0; o >>= 1) v += __shfl_xor_sync(0xffffffffu, v, o);
    if (lane == 0) wsum[w] = v;
    __syncthreads();
    if (t == 0) {
        int s = 0;
        #pragma unroll
        for (int k = 0; k < 8; k++) s += wsum[k];
        s_total = s;
    }
    __syncthreads();
    int idx = blockIdx.x * 256 + t;
    if (idx < NN) {
        int o = g_off[idx] + s_total;
        g_off[idx] = o;
        g_cur[idx] = o;
    }
}

__global__ __launch_bounds__(256) void scatter8_kernel(
    const int* __restrict__ srcp, const int* __restrict__ dstp, int E)
{
    int i = blockIdx.x * blockDim.x + threadIdx.x;
    int e8 = i * 8;
    if (e8 + 7 < E) {
        int4 sa = *(const int4*)(srcp + e8);
        int4 sb = *(const int4*)(srcp + e8 + 4);
        int4 da = *(const int4*)(dstp + e8);
        int4 db = *(const int4*)(dstp + e8 + 4);
        g_csr[atomicAdd(&g_cur[da.x], 1)] = sa.x;
        g_csr[atomicAdd(&g_cur[da.y], 1)] = sa.y;
        g_csr[atomicAdd(&g_cur[da.z], 1)] = sa.z;
        g_csr[atomicAdd(&g_cur[da.w], 1)] = sa.w;
        g_csr[atomicAdd(&g_cur[db.x], 1)] = sb.x;
        g_csr[atomicAdd(&g_cur[db.y], 1)] = sb.y;
        g_csr[atomicAdd(&g_cur[db.z], 1)] = sb.z;
        g_csr[atomicAdd(&g_cur[db.w], 1)] = sb.w;
    } else {
        for (int e = e8; e < E; e++)
            g_csr[atomicAdd(&g_cur[dstp[e]], 1)] = srcp[e];
    }
}

__global__ __launch_bounds__(256) void scatter1_kernel(
    const int* __restrict__ srcp, const int* __restrict__ dstp, int E)
{
    int e = blockIdx.x * blockDim.x + threadIdx.x;
    if (e < E) g_csr[atomicAdd(&g_cur[dstp[e]], 1)] = srcp[e];
}

// ---------------- layer 1 fused gather + self-loop + bias + BN + ELU --------
// lane covers 16 cols (two uint4 of 8 halves); 8 lanes per edge ->
// 4 edges in flight per shfl step.
__global__ __launch_bounds__(256) void agg1_kernel(
    const float* __restrict__ b1,
    const float* __restrict__ gamma, const float* __restrict__ beta,
    const float* __restrict__ mean,  const float* __restrict__ var, int E)
{
    int d = (blockIdx.x * blockDim.x + threadIdx.x) >> 5;
    int lane = threadIdx.x & 31;
    if (d >= NN) return;

    int sub = lane & 7;      // column group: cols [sub*16, sub*16+16)
    int grp = lane >> 3;     // 0..3: edge parity
    int h = sub >> 1;        // head of this 16-col group (16 | 32 alignment)
    float ad = g_adst1[d * 4 + h];

    int start = g_off[d];
    int end   = (d + 1 < NN) ? g_off[d + 1] : E;

    float acc[16] = {};
    float ssum = 0.f;

    // self-loop term (grp 0 only; combined at the end)
    if (grp == 0) {
        float e0 = g_asrc1[d * 4 + h] + ad;
        float w0 = __expf(e0 > 0.f ? e0 : NEG * e0);
        ssum = w0;
        const __half* base = g_xw1h + (size_t)d * F1 + sub * 16;
        uint4 r0 = *(const uint4*)(base);
        uint4 r1 = *(const uint4*)(base + 8);
        float2 f;
        f = __half22float2(*(__half2*)&r0.x); acc[0]  = w0*f.x; acc[1]  = w0*f.y;
        f = __half22float2(*(__half2*)&r0.y); acc[2]  = w0*f.x; acc[3]  = w0*f.y;
        f = __half22float2(*(__half2*)&r0.z); acc[4]  = w0*f.x; acc[5]  = w0*f.y;
        f = __half22float2(*(__half2*)&r0.w); acc[6]  = w0*f.x; acc[7]  = w0*f.y;
        f = __half22float2(*(__half2*)&r1.x); acc[8]  = w0*f.x; acc[9]  = w0*f.y;
        f = __half22float2(*(__half2*)&r1.y); acc[10] = w0*f.x; acc[11] = w0*f.y;
        f = __half22float2(*(__half2*)&r1.z); acc[12] = w0*f.x; acc[13] = w0*f.y;
        f = __half22float2(*(__half2*)&r1.w); acc[14] = w0*f.x; acc[15] = w0*f.y;
    }

    for (int i = start; i < end; i += 32) {
        int cnt = min(end - i, 32);
        int sj = (lane < cnt) ? g_csr[i + lane] : 0;
        #pragma unroll 4
        for (int k = 0; k < cnt; k += 4) {
            int kk = k + grp;
            int sel = kk < cnt ? kk : 0;
            int s = __shfl_sync(0xffffffffu, sj, sel);
            if (kk < cnt) {
                float e = g_asrc1[s * 4 + h] + ad;
                float w = __expf(e > 0.f ? e : NEG * e);
                const __half* base = g_xw1h + (size_t)s * F1 + sub * 16;
                uint4 r0 = *(const uint4*)(base);
                uint4 r1 = *(const uint4*)(base + 8);
                ssum += w;
                float2 f;
                f = __half22float2(*(__half2*)&r0.x); acc[0]  = fmaf(w,f.x,acc[0]);  acc[1]  = fmaf(w,f.y,acc[1]);
                f = __half22float2(*(__half2*)&r0.y); acc[2]  = fmaf(w,f.x,acc[2]);  acc[3]  = fmaf(w,f.y,acc[3]);
                f = __half22float2(*(__half2*)&r0.z); acc[4]  = fmaf(w,f.x,acc[4]);  acc[5]  = fmaf(w,f.y,acc[5]);
                f = __half22float2(*(__half2*)&r0.w); acc[6]  = fmaf(w,f.x,acc[6]);  acc[7]  = fmaf(w,f.y,acc[7]);
                f = __half22float2(*(__half2*)&r1.x); acc[8]  = fmaf(w,f.x,acc[8]);  acc[9]  = fmaf(w,f.y,acc[9]);
                f = __half22float2(*(__half2*)&r1.y); acc[10] = fmaf(w,f.x,acc[10]); acc[11] = fmaf(w,f.y,acc[11]);
                f = __half22float2(*(__half2*)&r1.z); acc[12] = fmaf(w,f.x,acc[12]); acc[13] = fmaf(w,f.y,acc[13]);
                f = __half22float2(*(__half2*)&r1.w); acc[14] = fmaf(w,f.x,acc[14]); acc[15] = fmaf(w,f.y,acc[15]);
            }
        }
    }

    // combine the four edge-parity groups (same columns, disjoint edges)
    ssum += __shfl_xor_sync(0xffffffffu, ssum, 8);
    ssum += __shfl_xor_sync(0xffffffffu, ssum, 16);
    #pragma unroll
    for (int j = 0; j < 16; j++) {
        acc[j] += __shfl_xor_sync(0xffffffffu, acc[j], 8);
        acc[j] += __shfl_xor_sync(0xffffffffu, acc[j], 16);
    }

    if (grp == 0) {
        float inv = 1.f / (ssum + EPSV);
        int c0 = sub * 16;
        float o[16];
        #pragma unroll
        for (int j = 0; j < 16; j++) {
            int c = c0 + j;
            float hv = acc[j] * inv + b1[c];
            hv = (hv - mean[c]) * rsqrtf(var[c] + 1e-5f) * gamma[c] + beta[c];
            o[j] = hv > 0.f ? hv : expm1f(hv);
        }
        float* outp = g_h1 + (size_t)d * F1 + c0;
        *(float4*)(outp)      = make_float4(o[0],  o[1],  o[2],  o[3]);
        *(float4*)(outp + 4)  = make_float4(o[4],  o[5],  o[6],  o[7]);
        *(float4*)(outp + 8)  = make_float4(o[8],  o[9],  o[10], o[11]);
        *(float4*)(outp + 12) = make_float4(o[12], o[13], o[14], o[15]);
    }
}

// ---------------- layer 2 fused gather + self-loop + bias -> out ------------
// lane covers 16 cols; 4 lanes per edge -> 8 edges per shfl step.
__global__ __launch_bounds__(256) void agg2_kernel(
    float* __restrict__ out, const float* __restrict__ b2, int E)
{
    int d = (blockIdx.x * blockDim.x + threadIdx.x) >> 5;
    int lane = threadIdx.x & 31;
    if (d >= NN) return;

    int sub = lane & 3;      // column group: cols [sub*16, sub*16+16)
    int grp = lane >> 2;     // 0..7: edge parity
    float ad = g_adst2[d];

    int start = g_off[d];
    int end   = (d + 1 < NN) ? g_off[d + 1] : E;

    float acc[16] = {};
    float ssum = 0.f;

    if (grp == 0) {
        float e0 = g_asrc2[d] + ad;
        float w0 = __expf(e0 > 0.f ? e0 : NEG * e0);
        ssum = w0;
        const __half* base = g_xw2h + (size_t)d * F2 + sub * 16;
        uint4 r0 = *(const uint4*)(base);
        uint4 r1 = *(const uint4*)(base + 8);
        float2 f;
        f = __half22float2(*(__half2*)&r0.x); acc[0]  = w0*f.x; acc[1]  = w0*f.y;
        f = __half22float2(*(__half2*)&r0.y); acc[2]  = w0*f.x; acc[3]  = w0*f.y;
        f = __half22float2(*(__half2*)&r0.z); acc[4]  = w0*f.x; acc[5]  = w0*f.y;
        f = __half22float2(*(__half2*)&r0.w); acc[6]  = w0*f.x; acc[7]  = w0*f.y;
        f = __half22float2(*(__half2*)&r1.x); acc[8]  = w0*f.x; acc[9]  = w0*f.y;
        f = __half22float2(*(__half2*)&r1.y); acc[10] = w0*f.x; acc[11] = w0*f.y;
        f = __half22float2(*(__half2*)&r1.z); acc[12] = w0*f.x; acc[13] = w0*f.y;
        f = __half22float2(*(__half2*)&r1.w); acc[14] = w0*f.x; acc[15] = w0*f.y;
    }

    for (int i = start; i < end; i += 32) {
        int cnt = min(end - i, 32);
        int sj = (lane < cnt) ? g_csr[i + lane] : 0;
        #pragma unroll 2
        for (int k = 0; k < cnt; k += 8) {
            int kk = k + grp;
            int sel = kk < cnt ? kk : 0;
            int s = __shfl_sync(0xffffffffu, sj, sel);
            if (kk < cnt) {
                float e = g_asrc2[s] + ad;
                float w = __expf(e > 0.f ? e : NEG * e);
                const __half* base = g_xw2h + (size_t)s * F2 + sub * 16;
                uint4 r0 = *(const uint4*)(base);
                uint4 r1 = *(const uint4*)(base + 8);
                ssum += w;
                float2 f;
                f = __half22float2(*(__half2*)&r0.x); acc[0]  = fmaf(w,f.x,acc[0]);  acc[1]  = fmaf(w,f.y,acc[1]);
                f = __half22float2(*(__half2*)&r0.y); acc[2]  = fmaf(w,f.x,acc[2]);  acc[3]  = fmaf(w,f.y,acc[3]);
                f = __half22float2(*(__half2*)&r0.z); acc[4]  = fmaf(w,f.x,acc[4]);  acc[5]  = fmaf(w,f.y,acc[5]);
                f = __half22float2(*(__half2*)&r0.w); acc[6]  = fmaf(w,f.x,acc[6]);  acc[7]  = fmaf(w,f.y,acc[7]);
                f = __half22float2(*(__half2*)&r1.x); acc[8]  = fmaf(w,f.x,acc[8]);  acc[9]  = fmaf(w,f.y,acc[9]);
                f = __half22float2(*(__half2*)&r1.y); acc[10] = fmaf(w,f.x,acc[10]); acc[11] = fmaf(w,f.y,acc[11]);
                f = __half22float2(*(__half2*)&r1.z); acc[12] = fmaf(w,f.x,acc[12]); acc[13] = fmaf(w,f.y,acc[13]);
                f = __half22float2(*(__half2*)&r1.w); acc[14] = fmaf(w,f.x,acc[14]); acc[15] = fmaf(w,f.y,acc[15]);
            }
        }
    }

    // combine the eight edge-parity groups
    ssum += __shfl_xor_sync(0xffffffffu, ssum, 4);
    ssum += __shfl_xor_sync(0xffffffffu, ssum, 8);
    ssum += __shfl_xor_sync(0xffffffffu, ssum, 16);
    #pragma unroll
    for (int j = 0; j < 16; j++) {
        acc[j] += __shfl_xor_sync(0xffffffffu, acc[j], 4);
        acc[j] += __shfl_xor_sync(0xffffffffu, acc[j], 8);
        acc[j] += __shfl_xor_sync(0xffffffffu, acc[j], 16);
    }

    if (grp == 0) {
        float inv = 1.f / (ssum + EPSV);
        int c0 = sub * 16;
        float o[16];
        #pragma unroll
        for (int j = 0; j < 16; j++)
            o[j] = acc[j] * inv + b2[c0 + j];
        float* outp = out + (size_t)d * F2 + c0;
        *(float4*)(outp)      = make_float4(o[0],  o[1],  o[2],  o[3]);
        *(float4*)(outp + 4)  = make_float4(o[4],  o[5],  o[6],  o[7]);
        *(float4*)(outp + 8)  = make_float4(o[8],  o[9],  o[10], o[11]);
        *(float4*)(outp + 12) = make_float4(o[12], o[13], o[14], o[15]);
    }
}

// ---------------- launch ----------------------------------------------------
extern "C" void kernel_launch(void* const* d_in, const int* in_sizes, int n_in,
                              void* d_out, int out_size)
{
    const float* x        = (const float*)d_in[0];
    const int*   ei       = (const int*)  d_in[1];
    const float* W1       = (const float*)d_in[2];
    const float* att_src1 = (const float*)d_in[3];
    const float* att_dst1 = (const float*)d_in[4];
    const float* b1       = (const float*)d_in[5];
    const float* bn_gamma = (const float*)d_in[6];
    const float* bn_beta  = (const float*)d_in[7];
    const float* bn_mean  = (const float*)d_in[8];
    const float* bn_var   = (const float*)d_in[9];
    const float* W2       = (const float*)d_in[10];
    const float* att_src2 = (const float*)d_in[11];
    const float* att_dst2 = (const float*)d_in[12];
    const float* b2       = (const float*)d_in[13];
    float* out = (float*)d_out;

    int E  = in_sizes[1] / 2;
    const int* srcp = ei;
    const int* dstp = ei + E;

    float  *p_h1 = nullptr;
    __half *p_xw1h = nullptr, *p_xw2h = nullptr;
    cudaGetSymbolAddress((void**)&p_xw1h, g_xw1h);
    cudaGetSymbolAddress((void**)&p_h1,   g_h1);
    cudaGetSymbolAddress((void**)&p_xw2h, g_xw2h);

    static cudaStream_t s_side = nullptr;
    static cudaEvent_t ev_fork = nullptr, ev_join = nullptr;
    if (!s_side) {
        cudaStreamCreateWithFlags(&s_side, cudaStreamNonBlocking);
        cudaEventCreateWithFlags(&ev_fork, cudaEventDisableTiming);
        cudaEventCreateWithFlags(&ev_join, cudaEventDisableTiming);
    }

    bool vec_ok = (E % 4 == 0) &&
                  ((((uintptr_t)srcp) & 15u) == 0) &&
                  ((((uintptr_t)dstp) & 15u) == 0);

    // ---- fork: CSR build on side stream, GEMM1(+attn1) on main --------------
    cudaEventRecord(ev_fork, 0);
    cudaStreamWaitEvent(s_side, ev_fork, 0);

    if (vec_ok) {
        hist8_kernel<<<((E + 7) / 8 + 255) / 256, 256, 0, s_side>>>(dstp, E);
    } else {
        hist1_kernel<<<(E + 255) / 256, 256, 0, s_side>>>(dstp, E);
    }
    scanA_kernel<<<NBLK, 256, 0, s_side>>>();
    scanC_kernel<<<NBLK, 256, 0, s_side>>>();
    if (vec_ok) {
        scatter8_kernel<<<((E + 7) / 8 + 255) / 256, 256, 0, s_side>>>(srcp, dstp, E);
    } else {
        scatter1_kernel<<<(E + 255) / 256, 256, 0, s_side>>>(srcp, dstp, E);
    }

    {
        dim3 grid(1, (NN + 127) / 128);
        gemm1_kernel<<<grid, 256>>>(x, W1, p_xw1h, att_src1, att_dst1, NN);
    }

    // ---- join ----------------------------------------------------------------
    cudaEventRecord(ev_join, s_side);
    cudaStreamWaitEvent(0, ev_join, 0);

    // ---- layer 1 aggregate + layer 2 ------------------------------------------
    agg1_kernel<<<(NN * 32 + 255) / 256, 256>>>(b1, bn_gamma, bn_beta, bn_mean, bn_var, E);
    {
        dim3 grid(1, (NN + 127) / 128);
        gemm2_kernel<<<grid, 128>>>(p_h1, W2, p_xw2h, att_src2, att_dst2, NN);
    }
    agg2_kernel<<<(NN * 32 + 255) / 256, 256>>>(out, b2, E);
}

// round 13
// speedup vs baseline: 1.1744x; 1.1744x over previous
#include <cuda_runtime.h>
#include <cuda_fp16.h>
#include <math.h>
#include <stdint.h>

#define NN 50000
#define HH 4
#define CC 32
#define F1 128
#define F2 64
#define NEG 0.2f
#define EPSV 1e-16f
#define EMAX 1600000   // real edges only (self loops handled analytically)
#define NBLK ((NN + 255) / 256)

// ---------------- scratch (device globals; no allocations allowed) ----------
__device__ __align__(16) __half g_xw1h[NN * F1];  // x@W1 half (agg1 gather)
__device__ float  g_h1 [NN * F1];                 // layer1 output (gemm2 input)
__device__ float  g_asrc1[NN * HH];
__device__ float  g_adst1[NN * HH];
__device__ __align__(16) __half g_xw2h[NN * F2];  // h@W2 half (agg2 gather)
__device__ float  g_asrc2[NN];
__device__ float  g_adst2[NN];
__device__ int    g_deg[NN];          // ZERO before each use; scanA re-zeroes
__device__ int    g_off[NN];          // CSR segment start
__device__ int    g_cur[NN];          // scatter cursor
__device__ int    g_bsum[256];        // block sums for scan
__device__ int    g_csr[EMAX];        // src node per edge, grouped by dst

// ---------------- GEMM1: xw1h = half(x @ W1), fused attn1 -------------------
__global__ __launch_bounds__(256) void gemm1_kernel(
    const float* __restrict__ A, const float* __restrict__ B,
    __half* __restrict__ Ch,
    const float* __restrict__ att_src, const float* __restrict__ att_dst, int M)
{
    const int BM = 128, BN = 128, BK = 8, KTOT = 128, NT = 256, TX = 16;
    __shared__ float As[2][BK * BM];
    __shared__ float Bs[2][BK * BN];

    int tid = threadIdx.x;
    int tx = tid % TX;
    int ty = tid / TX;
    int row0 = blockIdx.y * BM;

    float acc[8][8] = {};

    auto load_tile = [&](int buf, int kt) {
        int k0 = kt * BK;
        #pragma unroll
        for (int idx = tid; idx < BM * BK / 4; idx += NT) {
            int row = idx >> 1;
            int kc  = (idx & 1) * 4;
            int gr = row0 + row;
            float4 v = make_float4(0.f, 0.f, 0.f, 0.f);
            if (gr < M) v = *(const float4*)(A + (size_t)gr * KTOT + k0 + kc);
            As[buf][(kc + 0) * BM + row] = v.x;
            As[buf][(kc + 1) * BM + row] = v.y;
            As[buf][(kc + 2) * BM + row] = v.z;
            As[buf][(kc + 3) * BM + row] = v.w;
        }
        #pragma unroll
        for (int idx = tid; idx < BK * BN / 4; idx += NT) {
            int r  = idx / (BN / 4);
            int c4 = (idx % (BN / 4)) * 4;
            *(float4*)&Bs[buf][r * BN + c4] =
                *(const float4*)(B + (size_t)(k0 + r) * BN + c4);
        }
    };

    load_tile(0, 0);
    __syncthreads();

    int buf = 0;
    for (int kt = 0; kt < KTOT / BK; kt++) {
        if (kt + 1 < KTOT / BK) load_tile(buf ^ 1, kt + 1);
        #pragma unroll
        for (int kk = 0; kk < BK; kk++) {
            float4 a0 = *(const float4*)&As[buf][kk * BM + ty * 8];
            float4 a1 = *(const float4*)&As[buf][kk * BM + ty * 8 + 4];
            float4 b0 = *(const float4*)&Bs[buf][kk * BN + tx * 8];
            float4 b1 = *(const float4*)&Bs[buf][kk * BN + tx * 8 + 4];
            float av[8] = {a0.x,a0.y,a0.z,a0.w,a1.x,a1.y,a1.z,a1.w};
            float bv[8] = {b0.x,b0.y,b0.z,b0.w,b1.x,b1.y,b1.z,b1.w};
            #pragma unroll
            for (int i = 0; i < 8; i++)
                #pragma unroll
                for (int j = 0; j < 8; j++)
                    acc[i][j] = fmaf(av[i], bv[j], acc[i][j]);
        }
        __syncthreads();
        buf ^= 1;
    }

    float as1[8], ad1[8];
    #pragma unroll
    for (int j = 0; j < 8; j++) {
        as1[j] = att_src[tx * 8 + j];
        ad1[j] = att_dst[tx * 8 + j];
    }
    int h = tx >> 2;

    #pragma unroll
    for (int i = 0; i < 8; i++) {
        int gr = row0 + ty * 8 + i;
        float ps = 0.f, pd = 0.f;
        #pragma unroll
        for (int j = 0; j < 8; j++) {
            ps = fmaf(acc[i][j], as1[j], ps);
            pd = fmaf(acc[i][j], ad1[j], pd);
        }
        ps += __shfl_xor_sync(0xffffffffu, ps, 1);
        pd += __shfl_xor_sync(0xffffffffu, pd, 1);
        ps += __shfl_xor_sync(0xffffffffu, ps, 2);
        pd += __shfl_xor_sync(0xffffffffu, pd, 2);
        if (gr < M) {
            __half2 p0 = __floats2half2_rn(acc[i][0], acc[i][1]);
            __half2 p1 = __floats2half2_rn(acc[i][2], acc[i][3]);
            __half2 p2 = __floats2half2_rn(acc[i][4], acc[i][5]);
            __half2 p3 = __floats2half2_rn(acc[i][6], acc[i][7]);
            uint4 u = make_uint4(*(unsigned*)&p0, *(unsigned*)&p1,
                                 *(unsigned*)&p2, *(unsigned*)&p3);
            *(uint4*)(Ch + (size_t)gr * BN + tx * 8) = u;
            if ((tx & 3) == 0) {
                g_asrc1[gr * 4 + h] = ps;
                g_adst1[gr * 4 + h] = pd;
            }
        }
    }
}

// ---------------- GEMM2: xw2h = half(h1 @ W2), fused attn2 ------------------
__global__ __launch_bounds__(128) void gemm2_kernel(
    const float* __restrict__ A, const float* __restrict__ B,
    __half* __restrict__ Ch,
    const float* __restrict__ att_src, const float* __restrict__ att_dst, int M)
{
    const int BM = 128, BN = 64, BK = 8, KTOT = 128, NT = 128, TX = 8;
    __shared__ float As[2][BK * BM];
    __shared__ float Bs[2][BK * BN];

    int tid = threadIdx.x;
    int tx = tid % TX;
    int ty = tid / TX;
    int row0 = blockIdx.y * BM;

    float acc[8][8] = {};

    auto load_tile = [&](int buf, int kt) {
        int k0 = kt * BK;
        #pragma unroll
        for (int idx = tid; idx < BM * BK / 4; idx += NT) {
            int row = idx >> 1;
            int kc  = (idx & 1) * 4;
            int gr = row0 + row;
            float4 v = make_float4(0.f, 0.f, 0.f, 0.f);
            if (gr < M) v = *(const float4*)(A + (size_t)gr * KTOT + k0 + kc);
            As[buf][(kc + 0) * BM + row] = v.x;
            As[buf][(kc + 1) * BM + row] = v.y;
            As[buf][(kc + 2) * BM + row] = v.z;
            As[buf][(kc + 3) * BM + row] = v.w;
        }
        #pragma unroll
        for (int idx = tid; idx < BK * BN / 4; idx += NT) {
            int r  = idx / (BN / 4);
            int c4 = (idx % (BN / 4)) * 4;
            *(float4*)&Bs[buf][r * BN + c4] =
                *(const float4*)(B + (size_t)(k0 + r) * BN + c4);
        }
    };

    load_tile(0, 0);
    __syncthreads();

    int buf = 0;
    for (int kt = 0; kt < KTOT / BK; kt++) {
        if (kt + 1 < KTOT / BK) load_tile(buf ^ 1, kt + 1);
        #pragma unroll
        for (int kk = 0; kk < BK; kk++) {
            float4 a0 = *(const float4*)&As[buf][kk * BM + ty * 8];
            float4 a1 = *(const float4*)&As[buf][kk * BM + ty * 8 + 4];
            float4 b0 = *(const float4*)&Bs[buf][kk * BN + tx * 8];
            float4 b1 = *(const float4*)&Bs[buf][kk * BN + tx * 8 + 4];
            float av[8] = {a0.x,a0.y,a0.z,a0.w,a1.x,a1.y,a1.z,a1.w};
            float bv[8] = {b0.x,b0.y,b0.z,b0.w,b1.x,b1.y,b1.z,b1.w};
            #pragma unroll
            for (int i = 0; i < 8; i++)
                #pragma unroll
                for (int j = 0; j < 8; j++)
                    acc[i][j] = fmaf(av[i], bv[j], acc[i][j]);
        }
        __syncthreads();
        buf ^= 1;
    }

    float as2[8], ad2[8];
    #pragma unroll
    for (int j = 0; j < 8; j++) {
        as2[j] = att_src[tx * 8 + j];
        ad2[j] = att_dst[tx * 8 + j];
    }

    #pragma unroll
    for (int i = 0; i < 8; i++) {
        int gr = row0 + ty * 8 + i;
        float ps = 0.f, pd = 0.f;
        #pragma unroll
        for (int j = 0; j < 8; j++) {
            ps = fmaf(acc[i][j], as2[j], ps);
            pd = fmaf(acc[i][j], ad2[j], pd);
        }
        ps += __shfl_xor_sync(0xffffffffu, ps, 1);
        pd += __shfl_xor_sync(0xffffffffu, pd, 1);
        ps += __shfl_xor_sync(0xffffffffu, ps, 2);
        pd += __shfl_xor_sync(0xffffffffu, pd, 2);
        ps += __shfl_xor_sync(0xffffffffu, ps, 4);
        pd += __shfl_xor_sync(0xffffffffu, pd, 4);
        if (gr < M) {
            __half2 p0 = __floats2half2_rn(acc[i][0], acc[i][1]);
            __half2 p1 = __floats2half2_rn(acc[i][2], acc[i][3]);
            __half2 p2 = __floats2half2_rn(acc[i][4], acc[i][5]);
            __half2 p3 = __floats2half2_rn(acc[i][6], acc[i][7]);
            uint4 u = make_uint4(*(unsigned*)&p0, *(unsigned*)&p1,
                                 *(unsigned*)&p2, *(unsigned*)&p3);
            *(uint4*)(Ch + (size_t)gr * BN + tx * 8) = u;
            if (tx == 0) {
                g_asrc2[gr] = ps;
                g_adst2[gr] = pd;
            }
        }
    }
}

// ---------------- CSR build (real edges only) -------------------------------
__global__ __launch_bounds__(256) void hist8_kernel(const int* __restrict__ dstp, int E) {
    int i = blockIdx.x * blockDim.x + threadIdx.x;
    int e8 = i * 8;
    if (e8 + 7 < E) {
        int4 a = *(const int4*)(dstp + e8);
        int4 b = *(const int4*)(dstp + e8 + 4);
        atomicAdd(&g_deg[a.x], 1); atomicAdd(&g_deg[a.y], 1);
        atomicAdd(&g_deg[a.z], 1); atomicAdd(&g_deg[a.w], 1);
        atomicAdd(&g_deg[b.x], 1); atomicAdd(&g_deg[b.y], 1);
        atomicAdd(&g_deg[b.z], 1); atomicAdd(&g_deg[b.w], 1);
    } else {
        for (int e = e8; e < E; e++) atomicAdd(&g_deg[dstp[e]], 1);
    }
}

__global__ __launch_bounds__(256) void hist1_kernel(const int* __restrict__ dstp, int E) {
    int e = blockIdx.x * blockDim.x + threadIdx.x;
    if (e < E) atomicAdd(&g_deg[dstp[e]], 1);
}

// per-block exclusive scan of g_deg -> g_off(local), g_bsum; zeroes g_deg
__global__ __launch_bounds__(256) void scanA_kernel() {
    __shared__ int wsum[8];
    int t = threadIdx.x, lane = t & 31, w = t >> 5;
    int idx = blockIdx.x * 256 + t;
    int v = (idx < NN) ? g_deg[idx] : 0;
    int x = v;
    #pragma unroll
    for (int o = 1; o < 32; o <<= 1) {
        int tt = __shfl_up_sync(0xffffffffu, x, o);
        if (lane >= o) x += tt;
    }
    if (lane == 31) wsum[w] = x;
    __syncthreads();
    if (w == 0) {
        int s = (lane < 8) ? wsum[lane] : 0;
        #pragma unroll
        for (int o = 1; o < 8; o <<= 1) {
            int tt = __shfl_up_sync(0xffffffffu, s, o);
            if (lane >= o) s += tt;
        }
        if (lane < 8) wsum[lane] = s;
    }
    __syncthreads();
    int pre = (w > 0 ? wsum[w - 1] : 0) + (x - v);
    if (idx < NN) {
        g_off[idx] = pre;
        g_deg[idx] = 0;               // self-clean for next invocation
    }
    if (t == 255) g_bsum[blockIdx.x] = pre + v;
}

// add block offset (reduce prefix of g_bsum inline), init cursors
__global__ __launch_bounds__(256) void scanC_kernel() {
    __shared__ int wsum[8];
    __shared__ int s_total;
    int t = threadIdx.x, lane = t & 31, w = t >> 5;
    int v = (t < (int)blockIdx.x && t < NBLK) ? g_bsum[t] : 0;
    #pragma unroll
    for (int o = 16; o > 0; o >>= 1) v += __shfl_xor_sync(0xffffffffu, v, o);
    if (lane == 0) wsum[w] = v;
    __syncthreads();
    if (t == 0) {
        int s = 0;
        #pragma unroll
        for (int k = 0; k < 8; k++) s += wsum[k];
        s_total = s;
    }
    __syncthreads();
    int idx = blockIdx.x * 256 + t;
    if (idx < NN) {
        int o = g_off[idx] + s_total;
        g_off[idx] = o;
        g_cur[idx] = o;
    }
}

__global__ __launch_bounds__(256) void scatter8_kernel(
    const int* __restrict__ srcp, const int* __restrict__ dstp, int E)
{
    int i = blockIdx.x * blockDim.x + threadIdx.x;
    int e8 = i * 8;
    if (e8 + 7 < E) {
        int4 sa = *(const int4*)(srcp + e8);
        int4 sb = *(const int4*)(srcp + e8 + 4);
        int4 da = *(const int4*)(dstp + e8);
        int4 db = *(const int4*)(dstp + e8 + 4);
        g_csr[atomicAdd(&g_cur[da.x], 1)] = sa.x;
        g_csr[atomicAdd(&g_cur[da.y], 1)] = sa.y;
        g_csr[atomicAdd(&g_cur[da.z], 1)] = sa.z;
        g_csr[atomicAdd(&g_cur[da.w], 1)] = sa.w;
        g_csr[atomicAdd(&g_cur[db.x], 1)] = sb.x;
        g_csr[atomicAdd(&g_cur[db.y], 1)] = sb.y;
        g_csr[atomicAdd(&g_cur[db.z], 1)] = sb.z;
        g_csr[atomicAdd(&g_cur[db.w], 1)] = sb.w;
    } else {
        for (int e = e8; e < E; e++)
            g_csr[atomicAdd(&g_cur[dstp[e]], 1)] = srcp[e];
    }
}

__global__ __launch_bounds__(256) void scatter1_kernel(
    const int* __restrict__ srcp, const int* __restrict__ dstp, int E)
{
    int e = blockIdx.x * blockDim.x + threadIdx.x;
    if (e < E) g_csr[atomicAdd(&g_cur[dstp[e]], 1)] = srcp[e];
}

// ---------------- layer 1 fused gather + self-loop + bias + BN + ELU --------
// lane covers 8 cols (one uint4 of 8 halves); half-warps process alternating
// edges -> 2 edges in flight per shfl step. CSR chunk loads double-buffered.
__global__ __launch_bounds__(256) void agg1_kernel(
    const float* __restrict__ b1,
    const float* __restrict__ gamma, const float* __restrict__ beta,
    const float* __restrict__ mean,  const float* __restrict__ var, int E)
{
    int d = (blockIdx.x * blockDim.x + threadIdx.x) >> 5;
    int lane = threadIdx.x & 31;
    if (d >= NN) return;

    int sub  = lane & 15;    // column group: cols [sub*8, sub*8+8)
    int half = lane >> 4;    // 0/1: which parity of edges this lane handles
    int h = sub >> 2;        // head of this column group
    float ad = g_adst1[d * 4 + h];

    int start = g_off[d];
    int end   = (d + 1 < NN) ? g_off[d + 1] : E;

    float acc[8] = {};
    float ssum = 0.f;

    // self-loop term (half 0 only; combined at the end)
    if (half == 0) {
        float e0 = g_asrc1[d * 4 + h] + ad;
        float w0 = __expf(e0 > 0.f ? e0 : NEG * e0);
        ssum = w0;
        uint4 raw = *(const uint4*)(g_xw1h + (size_t)d * F1 + sub * 8);
        float2 f0 = __half22float2(*(__half2*)&raw.x);
        float2 f1 = __half22float2(*(__half2*)&raw.y);
        float2 f2 = __half22float2(*(__half2*)&raw.z);
        float2 f3 = __half22float2(*(__half2*)&raw.w);
        acc[0] = w0 * f0.x; acc[1] = w0 * f0.y;
        acc[2] = w0 * f1.x; acc[3] = w0 * f1.y;
        acc[4] = w0 * f2.x; acc[5] = w0 * f2.y;
        acc[6] = w0 * f3.x; acc[7] = w0 * f3.y;
    }

    // prefetch first CSR chunk
    int sj = 0;
    if (start < end && lane < min(end - start, 32))
        sj = g_csr[start + lane];

    for (int i = start; i < end; i += 32) {
        int cnt = min(end - i, 32);
        int sj_cur = sj;
        // prefetch next chunk while processing current
        int inext = i + 32;
        if (inext < end) {
            int cnt2 = min(end - inext, 32);
            sj = (lane < cnt2) ? g_csr[inext + lane] : 0;
        }
        #pragma unroll 8
        for (int k = 0; k < cnt; k += 2) {
            int kk = k + half;
            int sel = kk < cnt ? kk : 0;           // converged shfl, clamped selector
            int s = __shfl_sync(0xffffffffu, sj_cur, sel);
            if (kk < cnt) {
                float e = g_asrc1[s * 4 + h] + ad;
                float w = __expf(e > 0.f ? e : NEG * e);
                uint4 raw = *(const uint4*)(g_xw1h + (size_t)s * F1 + sub * 8);
                float2 f0 = __half22float2(*(__half2*)&raw.x);
                float2 f1 = __half22float2(*(__half2*)&raw.y);
                float2 f2 = __half22float2(*(__half2*)&raw.z);
                float2 f3 = __half22float2(*(__half2*)&raw.w);
                ssum += w;
                acc[0] = fmaf(w, f0.x, acc[0]); acc[1] = fmaf(w, f0.y, acc[1]);
                acc[2] = fmaf(w, f1.x, acc[2]); acc[3] = fmaf(w, f1.y, acc[3]);
                acc[4] = fmaf(w, f2.x, acc[4]); acc[5] = fmaf(w, f2.y, acc[5]);
                acc[6] = fmaf(w, f3.x, acc[6]); acc[7] = fmaf(w, f3.y, acc[7]);
            }
        }
    }

    // combine the two half-warps (same columns, disjoint edge sets)
    ssum += __shfl_xor_sync(0xffffffffu, ssum, 16);
    #pragma unroll
    for (int j = 0; j < 8; j++)
        acc[j] += __shfl_xor_sync(0xffffffffu, acc[j], 16);

    if (half == 0) {
        float inv = 1.f / (ssum + EPSV);
        int c0 = sub * 8;
        float o[8];
        #pragma unroll
        for (int j = 0; j < 8; j++) {
            int c = c0 + j;
            float hv = acc[j] * inv + b1[c];
            hv = (hv - mean[c]) * rsqrtf(var[c] + 1e-5f) * gamma[c] + beta[c];
            o[j] = hv > 0.f ? hv : expm1f(hv);
        }
        float* outp = g_h1 + (size_t)d * F1 + c0;
        *(float4*)(outp)     = make_float4(o[0], o[1], o[2], o[3]);
        *(float4*)(outp + 4) = make_float4(o[4], o[5], o[6], o[7]);
    }
}

// ---------------- layer 2 fused gather + self-loop + bias -> out ------------
// lane covers 8 cols; quarter-warps process 4 edges per shfl step.
__global__ __launch_bounds__(256) void agg2_kernel(
    float* __restrict__ out, const float* __restrict__ b2, int E)
{
    int d = (blockIdx.x * blockDim.x + threadIdx.x) >> 5;
    int lane = threadIdx.x & 31;
    if (d >= NN) return;

    int sub  = lane & 7;     // column group: cols [sub*8, sub*8+8)
    int quad = lane >> 3;    // 0..3: edge parity
    float ad = g_adst2[d];

    int start = g_off[d];
    int end   = (d + 1 < NN) ? g_off[d + 1] : E;

    float acc[8] = {};
    float ssum = 0.f;

    if (quad == 0) {
        float e0 = g_asrc2[d] + ad;
        float w0 = __expf(e0 > 0.f ? e0 : NEG * e0);
        ssum = w0;
        uint4 raw = *(const uint4*)(g_xw2h + (size_t)d * F2 + sub * 8);
        float2 f0 = __half22float2(*(__half2*)&raw.x);
        float2 f1 = __half22float2(*(__half2*)&raw.y);
        float2 f2 = __half22float2(*(__half2*)&raw.z);
        float2 f3 = __half22float2(*(__half2*)&raw.w);
        acc[0] = w0 * f0.x; acc[1] = w0 * f0.y;
        acc[2] = w0 * f1.x; acc[3] = w0 * f1.y;
        acc[4] = w0 * f2.x; acc[5] = w0 * f2.y;
        acc[6] = w0 * f3.x; acc[7] = w0 * f3.y;
    }

    // prefetch first CSR chunk
    int sj = 0;
    if (start < end && lane < min(end - start, 32))
        sj = g_csr[start + lane];

    for (int i = start; i < end; i += 32) {
        int cnt = min(end - i, 32);
        int sj_cur = sj;
        int inext = i + 32;
        if (inext < end) {
            int cnt2 = min(end - inext, 32);
            sj = (lane < cnt2) ? g_csr[inext + lane] : 0;
        }
        #pragma unroll 4
        for (int k = 0; k < cnt; k += 4) {
            int kk = k + quad;
            int sel = kk < cnt ? kk : 0;
            int s = __shfl_sync(0xffffffffu, sj_cur, sel);
            if (kk < cnt) {
                float e = g_asrc2[s] + ad;
                float w = __expf(e > 0.f ? e : NEG * e);
                uint4 raw = *(const uint4*)(g_xw2h + (size_t)s * F2 + sub * 8);
                float2 f0 = __half22float2(*(__half2*)&raw.x);
                float2 f1 = __half22float2(*(__half2*)&raw.y);
                float2 f2 = __half22float2(*(__half2*)&raw.z);
                float2 f3 = __half22float2(*(__half2*)&raw.w);
                ssum += w;
                acc[0] = fmaf(w, f0.x, acc[0]); acc[1] = fmaf(w, f0.y, acc[1]);
                acc[2] = fmaf(w, f1.x, acc[2]); acc[3] = fmaf(w, f1.y, acc[3]);
                acc[4] = fmaf(w, f2.x, acc[4]); acc[5] = fmaf(w, f2.y, acc[5]);
                acc[6] = fmaf(w, f3.x, acc[6]); acc[7] = fmaf(w, f3.y, acc[7]);
            }
        }
    }

    // combine the four quarter-warps
    ssum += __shfl_xor_sync(0xffffffffu, ssum, 8);
    ssum += __shfl_xor_sync(0xffffffffu, ssum, 16);
    #pragma unroll
    for (int j = 0; j < 8; j++) {
        acc[j] += __shfl_xor_sync(0xffffffffu, acc[j], 8);
        acc[j] += __shfl_xor_sync(0xffffffffu, acc[j], 16);
    }

    if (quad == 0) {
        float inv = 1.f / (ssum + EPSV);
        int c0 = sub * 8;
        float o[8];
        #pragma unroll
        for (int j = 0; j < 8; j++)
            o[j] = acc[j] * inv + b2[c0 + j];
        float* outp = out + (size_t)d * F2 + c0;
        *(float4*)(outp)     = make_float4(o[0], o[1], o[2], o[3]);
        *(float4*)(outp + 4) = make_float4(o[4], o[5], o[6], o[7]);
    }
}

// ---------------- launch ----------------------------------------------------
extern "C" void kernel_launch(void* const* d_in, const int* in_sizes, int n_in,
                              void* d_out, int out_size)
{
    const float* x        = (const float*)d_in[0];
    const int*   ei       = (const int*)  d_in[1];
    const float* W1       = (const float*)d_in[2];
    const float* att_src1 = (const float*)d_in[3];
    const float* att_dst1 = (const float*)d_in[4];
    const float* b1       = (const float*)d_in[5];
    const float* bn_gamma = (const float*)d_in[6];
    const float* bn_beta  = (const float*)d_in[7];
    const float* bn_mean  = (const float*)d_in[8];
    const float* bn_var   = (const float*)d_in[9];
    const float* W2       = (const float*)d_in[10];
    const float* att_src2 = (const float*)d_in[11];
    const float* att_dst2 = (const float*)d_in[12];
    const float* b2       = (const float*)d_in[13];
    float* out = (float*)d_out;

    int E  = in_sizes[1] / 2;
    const int* srcp = ei;
    const int* dstp = ei + E;

    float  *p_h1 = nullptr;
    __half *p_xw1h = nullptr, *p_xw2h = nullptr;
    cudaGetSymbolAddress((void**)&p_xw1h, g_xw1h);
    cudaGetSymbolAddress((void**)&p_h1,   g_h1);
    cudaGetSymbolAddress((void**)&p_xw2h, g_xw2h);

    static cudaStream_t s_side = nullptr;
    static cudaEvent_t ev_fork = nullptr, ev_join = nullptr;
    if (!s_side) {
        cudaStreamCreateWithFlags(&s_side, cudaStreamNonBlocking);
        cudaEventCreateWithFlags(&ev_fork, cudaEventDisableTiming);
        cudaEventCreateWithFlags(&ev_join, cudaEventDisableTiming);
    }

    bool vec_ok = (E % 4 == 0) &&
                  ((((uintptr_t)srcp) & 15u) == 0) &&
                  ((((uintptr_t)dstp) & 15u) == 0);

    // ---- fork: CSR build on side stream, GEMM1(+attn1) on main --------------
    cudaEventRecord(ev_fork, 0);
    cudaStreamWaitEvent(s_side, ev_fork, 0);

    if (vec_ok) {
        hist8_kernel<<<((E + 7) / 8 + 255) / 256, 256, 0, s_side>>>(dstp, E);
    } else {
        hist1_kernel<<<(E + 255) / 256, 256, 0, s_side>>>(dstp, E);
    }
    scanA_kernel<<<NBLK, 256, 0, s_side>>>();
    scanC_kernel<<<NBLK, 256, 0, s_side>>>();
    if (vec_ok) {
        scatter8_kernel<<<((E + 7) / 8 + 255) / 256, 256, 0, s_side>>>(srcp, dstp, E);
    } else {
        scatter1_kernel<<<(E + 255) / 256, 256, 0, s_side>>>(srcp, dstp, E);
    }

    {
        dim3 grid(1, (NN + 127) / 128);
        gemm1_kernel<<<grid, 256>>>(x, W1, p_xw1h, att_src1, att_dst1, NN);
    }

    // ---- join ----------------------------------------------------------------
    cudaEventRecord(ev_join, s_side);
    cudaStreamWaitEvent(0, ev_join, 0);

    // ---- layer 1 aggregate + layer 2 ------------------------------------------
    agg1_kernel<<<(NN * 32 + 255) / 256, 256>>>(b1, bn_gamma, bn_beta, bn_mean, bn_var, E);
    {
        dim3 grid(1, (NN + 127) / 128);
        gemm2_kernel<<<grid, 128>>>(p_h1, W2, p_xw2h, att_src2, att_dst2, NN);
    }
    agg2_kernel<<<(NN * 32 + 255) / 256, 256>>>(out, b2, E);
}

// round 14
// speedup vs baseline: 1.2137x; 1.0335x over previous
#include <cuda_runtime.h>
#include <cuda_fp16.h>
#include <mma.h>
#include <math.h>
#include <stdint.h>

using namespace nvcuda;

#define NN 50000
#define HH 4
#define CC 32
#define F1 128
#define F2 64
#define NEG 0.2f
#define EPSV 1e-16f
#define EMAX 1600000   // real edges only (self loops handled analytically)
#define NBLK ((NN + 255) / 256)
#define NPAD 50048     // NN rounded up to multiple of 64 (wmma tile safety)

// ---------------- scratch (device globals; no allocations allowed) ----------
__device__ __align__(16) __half g_xw1h[NN * F1];   // x@W1 half (agg1 gather)
__device__ __align__(16) __half g_h1h[NPAD * F1];  // layer1 output, half (gemm2 A)
__device__ float  g_asrc1[NN * HH];
__device__ float  g_adst1[NN * HH];
__device__ __align__(16) __half g_xw2h[NN * F2];   // h@W2 half (agg2 gather)
__device__ __align__(16) __half g_w2h[F1 * F2];    // W2 converted to half
__device__ float  g_asrc2[NN];
__device__ float  g_adst2[NN];
__device__ int    g_deg[NN];          // ZERO before each use; scanA re-zeroes
__device__ int    g_off[NN];          // CSR segment start
__device__ int    g_cur[NN];          // scatter cursor
__device__ int    g_bsum[256];        // block sums for scan
__device__ int    g_csr[EMAX];        // src node per edge, grouped by dst

// ---------------- GEMM1: xw1h = half(x @ W1), fused attn1 -------------------
__global__ __launch_bounds__(256) void gemm1_kernel(
    const float* __restrict__ A, const float* __restrict__ B,
    __half* __restrict__ Ch,
    const float* __restrict__ att_src, const float* __restrict__ att_dst, int M)
{
    const int BM = 128, BN = 128, BK = 8, KTOT = 128, NT = 256, TX = 16;
    __shared__ float As[2][BK * BM];
    __shared__ float Bs[2][BK * BN];

    int tid = threadIdx.x;
    int tx = tid % TX;
    int ty = tid / TX;
    int row0 = blockIdx.y * BM;

    float acc[8][8] = {};

    auto load_tile = [&](int buf, int kt) {
        int k0 = kt * BK;
        #pragma unroll
        for (int idx = tid; idx < BM * BK / 4; idx += NT) {
            int row = idx >> 1;
            int kc  = (idx & 1) * 4;
            int gr = row0 + row;
            float4 v = make_float4(0.f, 0.f, 0.f, 0.f);
            if (gr < M) v = *(const float4*)(A + (size_t)gr * KTOT + k0 + kc);
            As[buf][(kc + 0) * BM + row] = v.x;
            As[buf][(kc + 1) * BM + row] = v.y;
            As[buf][(kc + 2) * BM + row] = v.z;
            As[buf][(kc + 3) * BM + row] = v.w;
        }
        #pragma unroll
        for (int idx = tid; idx < BK * BN / 4; idx += NT) {
            int r  = idx / (BN / 4);
            int c4 = (idx % (BN / 4)) * 4;
            *(float4*)&Bs[buf][r * BN + c4] =
                *(const float4*)(B + (size_t)(k0 + r) * BN + c4);
        }
    };

    load_tile(0, 0);
    __syncthreads();

    int buf = 0;
    for (int kt = 0; kt < KTOT / BK; kt++) {
        if (kt + 1 < KTOT / BK) load_tile(buf ^ 1, kt + 1);
        #pragma unroll
        for (int kk = 0; kk < BK; kk++) {
            float4 a0 = *(const float4*)&As[buf][kk * BM + ty * 8];
            float4 a1 = *(const float4*)&As[buf][kk * BM + ty * 8 + 4];
            float4 b0 = *(const float4*)&Bs[buf][kk * BN + tx * 8];
            float4 b1 = *(const float4*)&Bs[buf][kk * BN + tx * 8 + 4];
            float av[8] = {a0.x,a0.y,a0.z,a0.w,a1.x,a1.y,a1.z,a1.w};
            float bv[8] = {b0.x,b0.y,b0.z,b0.w,b1.x,b1.y,b1.z,b1.w};
            #pragma unroll
            for (int i = 0; i < 8; i++)
                #pragma unroll
                for (int j = 0; j < 8; j++)
                    acc[i][j] = fmaf(av[i], bv[j], acc[i][j]);
        }
        __syncthreads();
        buf ^= 1;
    }

    float as1[8], ad1[8];
    #pragma unroll
    for (int j = 0; j < 8; j++) {
        as1[j] = att_src[tx * 8 + j];
        ad1[j] = att_dst[tx * 8 + j];
    }
    int h = tx >> 2;

    #pragma unroll
    for (int i = 0; i < 8; i++) {
        int gr = row0 + ty * 8 + i;
        float ps = 0.f, pd = 0.f;
        #pragma unroll
        for (int j = 0; j < 8; j++) {
            ps = fmaf(acc[i][j], as1[j], ps);
            pd = fmaf(acc[i][j], ad1[j], pd);
        }
        ps += __shfl_xor_sync(0xffffffffu, ps, 1);
        pd += __shfl_xor_sync(0xffffffffu, pd, 1);
        ps += __shfl_xor_sync(0xffffffffu, ps, 2);
        pd += __shfl_xor_sync(0xffffffffu, pd, 2);
        if (gr < M) {
            __half2 p0 = __floats2half2_rn(acc[i][0], acc[i][1]);
            __half2 p1 = __floats2half2_rn(acc[i][2], acc[i][3]);
            __half2 p2 = __floats2half2_rn(acc[i][4], acc[i][5]);
            __half2 p3 = __floats2half2_rn(acc[i][6], acc[i][7]);
            uint4 u = make_uint4(*(unsigned*)&p0, *(unsigned*)&p1,
                                 *(unsigned*)&p2, *(unsigned*)&p3);
            *(uint4*)(Ch + (size_t)gr * BN + tx * 8) = u;
            if ((tx & 3) == 0) {
                g_asrc1[gr * 4 + h] = ps;
                g_adst1[gr * 4 + h] = pd;
            }
        }
    }
}

// ---------------- W2 fp32 -> fp16 conversion --------------------------------
__global__ __launch_bounds__(256) void w2conv_kernel(const float* __restrict__ W2) {
    int i = blockIdx.x * blockDim.x + threadIdx.x;
    if (i < F1 * F2) g_w2h[i] = __float2half_rn(W2[i]);
}

// ---------------- GEMM2 (HMMA): xw2h = half(h1h @ W2h), fused attn2 ---------
// 4 warps per block; warp w computes rows [blk*64 + w*16, +16) x all 64 cols
// via wmma 16x16x16 fragments; epilogue through smem computes attn2 dots.
__global__ __launch_bounds__(128) void gemm2_wmma(
    const __half* __restrict__ A,      // g_h1h [NPAD,128]
    __half* __restrict__ Ch,           // g_xw2h [NN,64]
    const float* __restrict__ att_src, const float* __restrict__ att_dst, int M)
{
    __shared__ float sm[64 * 64];
    int tid  = threadIdx.x;
    int warp = tid >> 5;
    int blk0 = blockIdx.x * 64;
    int row0 = blk0 + warp * 16;

    wmma::fragment<wmma::accumulator, 16, 16, 16, float> acc[4];
    #pragma unroll
    for (int n = 0; n < 4; n++) wmma::fill_fragment(acc[n], 0.f);

    wmma::fragment<wmma::matrix_a, 16, 16, 16, __half, wmma::row_major> afrag;
    wmma::fragment<wmma::matrix_b, 16, 16, 16, __half, wmma::row_major> bfrag;

    #pragma unroll
    for (int k0 = 0; k0 < F1; k0 += 16) {
        wmma::load_matrix_sync(afrag, A + (size_t)row0 * F1 + k0, F1);
        #pragma unroll
        for (int n = 0; n < 4; n++) {
            wmma::load_matrix_sync(bfrag, g_w2h + (size_t)k0 * F2 + n * 16, F2);
            wmma::mma_sync(acc[n], afrag, bfrag, acc[n]);
        }
    }

    #pragma unroll
    for (int n = 0; n < 4; n++)
        wmma::store_matrix_sync(&sm[warp * 16 * 64 + n * 16], acc[n], 64,
                                wmma::mem_row_major);
    __syncthreads();

    // epilogue: 2 threads per row, each covers 32 cols
    int r    = tid >> 1;
    int halfi = tid & 1;
    int gr = blk0 + r;
    const float* rowp = &sm[r * 64 + halfi * 32];
    const float* asp = att_src + halfi * 32;
    const float* adp = att_dst + halfi * 32;

    float ps = 0.f, pd = 0.f;
    float v[32];
    #pragma unroll
    for (int j = 0; j < 32; j++) {
        v[j] = rowp[j];
        ps = fmaf(v[j], asp[j], ps);
        pd = fmaf(v[j], adp[j], pd);
    }
    ps += __shfl_xor_sync(0xffffffffu, ps, 1);
    pd += __shfl_xor_sync(0xffffffffu, pd, 1);

    if (gr < M) {
        #pragma unroll
        for (int c = 0; c < 4; c++) {
            __half2 p0 = __floats2half2_rn(v[c*8+0], v[c*8+1]);
            __half2 p1 = __floats2half2_rn(v[c*8+2], v[c*8+3]);
            __half2 p2 = __floats2half2_rn(v[c*8+4], v[c*8+5]);
            __half2 p3 = __floats2half2_rn(v[c*8+6], v[c*8+7]);
            uint4 u = make_uint4(*(unsigned*)&p0, *(unsigned*)&p1,
                                 *(unsigned*)&p2, *(unsigned*)&p3);
            *(uint4*)(Ch + (size_t)gr * F2 + halfi * 32 + c * 8) = u;
        }
        if (halfi == 0) {
            g_asrc2[gr] = ps;
            g_adst2[gr] = pd;
        }
    }
}

// ---------------- CSR build (real edges only) -------------------------------
__global__ __launch_bounds__(256) void hist8_kernel(const int* __restrict__ dstp, int E) {
    int i = blockIdx.x * blockDim.x + threadIdx.x;
    int e8 = i * 8;
    if (e8 + 7 < E) {
        int4 a = *(const int4*)(dstp + e8);
        int4 b = *(const int4*)(dstp + e8 + 4);
        atomicAdd(&g_deg[a.x], 1); atomicAdd(&g_deg[a.y], 1);
        atomicAdd(&g_deg[a.z], 1); atomicAdd(&g_deg[a.w], 1);
        atomicAdd(&g_deg[b.x], 1); atomicAdd(&g_deg[b.y], 1);
        atomicAdd(&g_deg[b.z], 1); atomicAdd(&g_deg[b.w], 1);
    } else {
        for (int e = e8; e < E; e++) atomicAdd(&g_deg[dstp[e]], 1);
    }
}

__global__ __launch_bounds__(256) void hist1_kernel(const int* __restrict__ dstp, int E) {
    int e = blockIdx.x * blockDim.x + threadIdx.x;
    if (e < E) atomicAdd(&g_deg[dstp[e]], 1);
}

// per-block exclusive scan of g_deg -> g_off(local), g_bsum; zeroes g_deg
__global__ __launch_bounds__(256) void scanA_kernel() {
    __shared__ int wsum[8];
    int t = threadIdx.x, lane = t & 31, w = t >> 5;
    int idx = blockIdx.x * 256 + t;
    int v = (idx < NN) ? g_deg[idx] : 0;
    int x = v;
    #pragma unroll
    for (int o = 1; o < 32; o <<= 1) {
        int tt = __shfl_up_sync(0xffffffffu, x, o);
        if (lane >= o) x += tt;
    }
    if (lane == 31) wsum[w] = x;
    __syncthreads();
    if (w == 0) {
        int s = (lane < 8) ? wsum[lane] : 0;
        #pragma unroll
        for (int o = 1; o < 8; o <<= 1) {
            int tt = __shfl_up_sync(0xffffffffu, s, o);
            if (lane >= o) s += tt;
        }
        if (lane < 8) wsum[lane] = s;
    }
    __syncthreads();
    int pre = (w > 0 ? wsum[w - 1] : 0) + (x - v);
    if (idx < NN) {
        g_off[idx] = pre;
        g_deg[idx] = 0;               // self-clean for next invocation
    }
    if (t == 255) g_bsum[blockIdx.x] = pre + v;
}

// add block offset (reduce prefix of g_bsum inline), init cursors
__global__ __launch_bounds__(256) void scanC_kernel() {
    __shared__ int wsum[8];
    __shared__ int s_total;
    int t = threadIdx.x, lane = t & 31, w = t >> 5;
    int v = (t < (int)blockIdx.x && t < NBLK) ? g_bsum[t] : 0;
    #pragma unroll
    for (int o = 16; o > 0; o >>= 1) v += __shfl_xor_sync(0xffffffffu, v, o);
    if (lane == 0) wsum[w] = v;
    __syncthreads();
    if (t == 0) {
        int s = 0;
        #pragma unroll
        for (int k = 0; k < 8; k++) s += wsum[k];
        s_total = s;
    }
    __syncthreads();
    int idx = blockIdx.x * 256 + t;
    if (idx < NN) {
        int o = g_off[idx] + s_total;
        g_off[idx] = o;
        g_cur[idx] = o;
    }
}

__global__ __launch_bounds__(256) void scatter8_kernel(
    const int* __restrict__ srcp, const int* __restrict__ dstp, int E)
{
    int i = blockIdx.x * blockDim.x + threadIdx.x;
    int e8 = i * 8;
    if (e8 + 7 < E) {
        int4 sa = *(const int4*)(srcp + e8);
        int4 sb = *(const int4*)(srcp + e8 + 4);
        int4 da = *(const int4*)(dstp + e8);
        int4 db = *(const int4*)(dstp + e8 + 4);
        g_csr[atomicAdd(&g_cur[da.x], 1)] = sa.x;
        g_csr[atomicAdd(&g_cur[da.y], 1)] = sa.y;
        g_csr[atomicAdd(&g_cur[da.z], 1)] = sa.z;
        g_csr[atomicAdd(&g_cur[da.w], 1)] = sa.w;
        g_csr[atomicAdd(&g_cur[db.x], 1)] = sb.x;
        g_csr[atomicAdd(&g_cur[db.y], 1)] = sb.y;
        g_csr[atomicAdd(&g_cur[db.z], 1)] = sb.z;
        g_csr[atomicAdd(&g_cur[db.w], 1)] = sb.w;
    } else {
        for (int e = e8; e < E; e++)
            g_csr[atomicAdd(&g_cur[dstp[e]], 1)] = srcp[e];
    }
}

__global__ __launch_bounds__(256) void scatter1_kernel(
    const int* __restrict__ srcp, const int* __restrict__ dstp, int E)
{
    int e = blockIdx.x * blockDim.x + threadIdx.x;
    if (e < E) g_csr[atomicAdd(&g_cur[dstp[e]], 1)] = srcp[e];
}

// ---------------- layer 1 fused gather + self-loop + bias + BN + ELU --------
// (R11 geometry) lane covers 8 cols; half-warps process alternating edges.
// Output written as fp16 into g_h1h (gemm2's HMMA input).
__global__ __launch_bounds__(256) void agg1_kernel(
    const float* __restrict__ b1,
    const float* __restrict__ gamma, const float* __restrict__ beta,
    const float* __restrict__ mean,  const float* __restrict__ var, int E)
{
    int d = (blockIdx.x * blockDim.x + threadIdx.x) >> 5;
    int lane = threadIdx.x & 31;
    if (d >= NN) return;

    int sub  = lane & 15;    // column group: cols [sub*8, sub*8+8)
    int half = lane >> 4;    // 0/1: which parity of edges this lane handles
    int h = sub >> 2;        // head of this column group
    float ad = g_adst1[d * 4 + h];

    int start = g_off[d];
    int end   = (d + 1 < NN) ? g_off[d + 1] : E;

    float acc[8] = {};
    float ssum = 0.f;

    // self-loop term (half 0 only; combined at the end)
    if (half == 0) {
        float e0 = g_asrc1[d * 4 + h] + ad;
        float w0 = __expf(e0 > 0.f ? e0 : NEG * e0);
        ssum = w0;
        uint4 raw = *(const uint4*)(g_xw1h + (size_t)d * F1 + sub * 8);
        float2 f0 = __half22float2(*(__half2*)&raw.x);
        float2 f1 = __half22float2(*(__half2*)&raw.y);
        float2 f2 = __half22float2(*(__half2*)&raw.z);
        float2 f3 = __half22float2(*(__half2*)&raw.w);
        acc[0] = w0 * f0.x; acc[1] = w0 * f0.y;
        acc[2] = w0 * f1.x; acc[3] = w0 * f1.y;
        acc[4] = w0 * f2.x; acc[5] = w0 * f2.y;
        acc[6] = w0 * f3.x; acc[7] = w0 * f3.y;
    }

    for (int i = start; i < end; i += 32) {
        int cnt = min(end - i, 32);
        int sj = (lane < cnt) ? g_csr[i + lane] : 0;
        #pragma unroll 8
        for (int k = 0; k < cnt; k += 2) {
            int kk = k + half;
            int sel = kk < cnt ? kk : 0;
            int s = __shfl_sync(0xffffffffu, sj, sel);
            if (kk < cnt) {
                float e = g_asrc1[s * 4 + h] + ad;
                float w = __expf(e > 0.f ? e : NEG * e);
                uint4 raw = *(const uint4*)(g_xw1h + (size_t)s * F1 + sub * 8);
                float2 f0 = __half22float2(*(__half2*)&raw.x);
                float2 f1 = __half22float2(*(__half2*)&raw.y);
                float2 f2 = __half22float2(*(__half2*)&raw.z);
                float2 f3 = __half22float2(*(__half2*)&raw.w);
                ssum += w;
                acc[0] = fmaf(w, f0.x, acc[0]); acc[1] = fmaf(w, f0.y, acc[1]);
                acc[2] = fmaf(w, f1.x, acc[2]); acc[3] = fmaf(w, f1.y, acc[3]);
                acc[4] = fmaf(w, f2.x, acc[4]); acc[5] = fmaf(w, f2.y, acc[5]);
                acc[6] = fmaf(w, f3.x, acc[6]); acc[7] = fmaf(w, f3.y, acc[7]);
            }
        }
    }

    // combine the two half-warps (same columns, disjoint edge sets)
    ssum += __shfl_xor_sync(0xffffffffu, ssum, 16);
    #pragma unroll
    for (int j = 0; j < 8; j++)
        acc[j] += __shfl_xor_sync(0xffffffffu, acc[j], 16);

    if (half == 0) {
        float inv = 1.f / (ssum + EPSV);
        int c0 = sub * 8;
        float o[8];
        #pragma unroll
        for (int j = 0; j < 8; j++) {
            int c = c0 + j;
            float hv = acc[j] * inv + b1[c];
            hv = (hv - mean[c]) * rsqrtf(var[c] + 1e-5f) * gamma[c] + beta[c];
            o[j] = hv > 0.f ? hv : expm1f(hv);
        }
        __half2 p0 = __floats2half2_rn(o[0], o[1]);
        __half2 p1 = __floats2half2_rn(o[2], o[3]);
        __half2 p2 = __floats2half2_rn(o[4], o[5]);
        __half2 p3 = __floats2half2_rn(o[6], o[7]);
        uint4 u = make_uint4(*(unsigned*)&p0, *(unsigned*)&p1,
                             *(unsigned*)&p2, *(unsigned*)&p3);
        *(uint4*)(g_h1h + (size_t)d * F1 + c0) = u;
    }
}

// ---------------- layer 2 fused gather + self-loop + bias -> out ------------
// (R11 geometry) lane covers 8 cols; quarter-warps process 4 edges per step.
__global__ __launch_bounds__(256) void agg2_kernel(
    float* __restrict__ out, const float* __restrict__ b2, int E)
{
    int d = (blockIdx.x * blockDim.x + threadIdx.x) >> 5;
    int lane = threadIdx.x & 31;
    if (d >= NN) return;

    int sub  = lane & 7;     // column group: cols [sub*8, sub*8+8)
    int quad = lane >> 3;    // 0..3: edge parity
    float ad = g_adst2[d];

    int start = g_off[d];
    int end   = (d + 1 < NN) ? g_off[d + 1] : E;

    float acc[8] = {};
    float ssum = 0.f;

    if (quad == 0) {
        float e0 = g_asrc2[d] + ad;
        float w0 = __expf(e0 > 0.f ? e0 : NEG * e0);
        ssum = w0;
        uint4 raw = *(const uint4*)(g_xw2h + (size_t)d * F2 + sub * 8);
        float2 f0 = __half22float2(*(__half2*)&raw.x);
        float2 f1 = __half22float2(*(__half2*)&raw.y);
        float2 f2 = __half22float2(*(__half2*)&raw.z);
        float2 f3 = __half22float2(*(__half2*)&raw.w);
        acc[0] = w0 * f0.x; acc[1] = w0 * f0.y;
        acc[2] = w0 * f1.x; acc[3] = w0 * f1.y;
        acc[4] = w0 * f2.x; acc[5] = w0 * f2.y;
        acc[6] = w0 * f3.x; acc[7] = w0 * f3.y;
    }

    for (int i = start; i < end; i += 32) {
        int cnt = min(end - i, 32);
        int sj = (lane < cnt) ? g_csr[i + lane] : 0;
        #pragma unroll 4
        for (int k = 0; k < cnt; k += 4) {
            int kk = k + quad;
            int sel = kk < cnt ? kk : 0;
            int s = __shfl_sync(0xffffffffu, sj, sel);
            if (kk < cnt) {
                float e = g_asrc2[s] + ad;
                float w = __expf(e > 0.f ? e : NEG * e);
                uint4 raw = *(const uint4*)(g_xw2h + (size_t)s * F2 + sub * 8);
                float2 f0 = __half22float2(*(__half2*)&raw.x);
                float2 f1 = __half22float2(*(__half2*)&raw.y);
                float2 f2 = __half22float2(*(__half2*)&raw.z);
                float2 f3 = __half22float2(*(__half2*)&raw.w);
                ssum += w;
                acc[0] = fmaf(w, f0.x, acc[0]); acc[1] = fmaf(w, f0.y, acc[1]);
                acc[2] = fmaf(w, f1.x, acc[2]); acc[3] = fmaf(w, f1.y, acc[3]);
                acc[4] = fmaf(w, f2.x, acc[4]); acc[5] = fmaf(w, f2.y, acc[5]);
                acc[6] = fmaf(w, f3.x, acc[6]); acc[7] = fmaf(w, f3.y, acc[7]);
            }
        }
    }

    // combine the four quarter-warps
    ssum += __shfl_xor_sync(0xffffffffu, ssum, 8);
    ssum += __shfl_xor_sync(0xffffffffu, ssum, 16);
    #pragma unroll
    for (int j = 0; j < 8; j++) {
        acc[j] += __shfl_xor_sync(0xffffffffu, acc[j], 8);
        acc[j] += __shfl_xor_sync(0xffffffffu, acc[j], 16);
    }

    if (quad == 0) {
        float inv = 1.f / (ssum + EPSV);
        int c0 = sub * 8;
        float o[8];
        #pragma unroll
        for (int j = 0; j < 8; j++)
            o[j] = acc[j] * inv + b2[c0 + j];
        float* outp = out + (size_t)d * F2 + c0;
        *(float4*)(outp)     = make_float4(o[0], o[1], o[2], o[3]);
        *(float4*)(outp + 4) = make_float4(o[4], o[5], o[6], o[7]);
    }
}

// ---------------- launch ----------------------------------------------------
extern "C" void kernel_launch(void* const* d_in, const int* in_sizes, int n_in,
                              void* d_out, int out_size)
{
    const float* x        = (const float*)d_in[0];
    const int*   ei       = (const int*)  d_in[1];
    const float* W1       = (const float*)d_in[2];
    const float* att_src1 = (const float*)d_in[3];
    const float* att_dst1 = (const float*)d_in[4];
    const float* b1       = (const float*)d_in[5];
    const float* bn_gamma = (const float*)d_in[6];
    const float* bn_beta  = (const float*)d_in[7];
    const float* bn_mean  = (const float*)d_in[8];
    const float* bn_var   = (const float*)d_in[9];
    const float* W2       = (const float*)d_in[10];
    const float* att_src2 = (const float*)d_in[11];
    const float* att_dst2 = (const float*)d_in[12];
    const float* b2       = (const float*)d_in[13];
    float* out = (float*)d_out;

    int E  = in_sizes[1] / 2;
    const int* srcp = ei;
    const int* dstp = ei + E;

    __half *p_xw1h = nullptr, *p_xw2h = nullptr, *p_h1h = nullptr;
    cudaGetSymbolAddress((void**)&p_xw1h, g_xw1h);
    cudaGetSymbolAddress((void**)&p_h1h,  g_h1h);
    cudaGetSymbolAddress((void**)&p_xw2h, g_xw2h);

    static cudaStream_t s_side = nullptr;
    static cudaEvent_t ev_fork = nullptr, ev_join = nullptr;
    if (!s_side) {
        cudaStreamCreateWithFlags(&s_side, cudaStreamNonBlocking);
        cudaEventCreateWithFlags(&ev_fork, cudaEventDisableTiming);
        cudaEventCreateWithFlags(&ev_join, cudaEventDisableTiming);
    }

    bool vec_ok = (E % 4 == 0) &&
                  ((((uintptr_t)srcp) & 15u) == 0) &&
                  ((((uintptr_t)dstp) & 15u) == 0);

    // ---- fork: CSR build + W2 conversion on side stream; GEMM1 on main ------
    cudaEventRecord(ev_fork, 0);
    cudaStreamWaitEvent(s_side, ev_fork, 0);

    w2conv_kernel<<<(F1 * F2 + 255) / 256, 256, 0, s_side>>>(W2);
    if (vec_ok) {
        hist8_kernel<<<((E + 7) / 8 + 255) / 256, 256, 0, s_side>>>(dstp, E);
    } else {
        hist1_kernel<<<(E + 255) / 256, 256, 0, s_side>>>(dstp, E);
    }
    scanA_kernel<<<NBLK, 256, 0, s_side>>>();
    scanC_kernel<<<NBLK, 256, 0, s_side>>>();
    if (vec_ok) {
        scatter8_kernel<<<((E + 7) / 8 + 255) / 256, 256, 0, s_side>>>(srcp, dstp, E);
    } else {
        scatter1_kernel<<<(E + 255) / 256, 256, 0, s_side>>>(srcp, dstp, E);
    }

    {
        dim3 grid(1, (NN + 127) / 128);
        gemm1_kernel<<<grid, 256>>>(x, W1, p_xw1h, att_src1, att_dst1, NN);
    }

    // ---- join ----------------------------------------------------------------
    cudaEventRecord(ev_join, s_side);
    cudaStreamWaitEvent(0, ev_join, 0);

    // ---- layer 1 aggregate + layer 2 ------------------------------------------
    agg1_kernel<<<(NN * 32 + 255) / 256, 256>>>(b1, bn_gamma, bn_beta, bn_mean, bn_var, E);
    gemm2_wmma<<<(NN + 63) / 64, 128>>>(p_h1h, p_xw2h, att_src2, att_dst2, NN);
    agg2_kernel<<<(NN * 32 + 255) / 256, 256>>>(out, b2, E);
}